// round 13
// baseline (speedup 1.0000x reference)
#include <cuda_runtime.h>
#include <cstdint>
#include <math.h>

#define EPS 1e-8f
#define RAD2DEG 57.295779513082320876798154814105f

#define THREADS    128
#define TILE_ROWS  128
#define CHUNK      32         // rows per item; item = 32 rows x 64 cols = 8KB CONTIGUOUS
#define NBUF       3          // ring depth (>= prefetch distance 2 + 1)
#define BUF_F      (CHUNK * 64)   // floats per buffer (8KB)

// Inputs: data [N,64] f32, lab [N,3] f32, W [64,3] f32, b [3] f32 ; out [N] f32
//
// Persistent CTAs + dynamic work stealing (self-resetting ticket counter).
// Each pipeline item is a ROW-chunk: 32 full rows = one contiguous 8KB DRAM
// block per cp.async group (perfect 128B-line, single-touch streaming),
// vs the previous column-quarter scheme whose 64B strided segments split
// every line into two requests. Compute: 4 lanes per row, slots 4k+a,
// 2-step shfl_xor reduction, epilogue on lane a==0.
// Smem swizzle: physical float4 slot = s ^ (4*(r&1)) -> every 8-lane
// LDS.128/STS phase covers all 32 banks.

__device__ unsigned int g_tile_ctr = 0;   // tickets (tile = gridDim.x + k)
__device__ unsigned int g_done_ctr = 0;   // CTAs finished

__device__ __forceinline__ void cp_async16(unsigned int dst, const void* src) {
    asm volatile("cp.async.cg.shared.global [%0], [%1], 16;\n"
                 :: "r"(dst), "l"(src));
}
__device__ __forceinline__ void cp_commit() {
    asm volatile("cp.async.commit_group;\n");
}
template <int n>
__device__ __forceinline__ void cp_wait() {
    asm volatile("cp.async.wait_group %0;\n" :: "n"(n));
}

__global__ __launch_bounds__(THREADS, 8) void cosine_loss_kernel(
    const float* __restrict__ data,
    const float* __restrict__ lab,
    const float* __restrict__ W,
    const float* __restrict__ b,
    float* __restrict__ out,
    int N, int ntiles)
{
    __shared__ __align__(16) float sbuf[NBUF][BUF_F];     // 3 x 8KB
    __shared__ __align__(16) float sW[3][64];
    __shared__ float sb[3];
    __shared__ int s_next;

    const int t = threadIdx.x;
    const int nblk = (int)gridDim.x;

    if (t < 192) { int k = t / 3, c = t % 3; sW[c][k] = W[t]; }
    {
        int i = t + 128;
        if (i < 192) { int k = i / 3, c = i % 3; sW[c][k] = W[i]; }
    }
    if (t < 3) sb[t] = b[t];

    int tile_cur = blockIdx.x;
    if (t == 0) s_next = nblk + (int)atomicAdd(&g_tile_ctr, 1u);
    __syncthreads();                       // W/b staged + s_next visible
    int tile_next = s_next;

    // Stage row-chunk q of `tile` (rows q*32..q*32+31, all 64 cols) into
    // sbuf[slot] as one contiguous 8KB cp.async group.
    auto prefetch = [&](int tile, int q, int slot) {
        if (tile >= ntiles) { cp_commit(); return; }
        int row0 = tile * TILE_ROWS + q * CHUNK;
        const float4* gsrc =
            reinterpret_cast<const float4*>(data) + (size_t)row0 * 16;
        unsigned int sdst =
            (unsigned int)__cvta_generic_to_shared(&sbuf[slot][0]);
        #pragma unroll
        for (int j = 0; j < 4; ++j) {
            int v = j * THREADS + t;          // 0..511 float4 in 8KB chunk
            int r = v >> 4;                   // local row 0..31
            int s = v & 15;                   // float4 slot within row
            int ps = s ^ ((r & 1) << 2);      // swizzled physical slot
            if (row0 + r < N) {
                cp_async16(sdst + (unsigned int)((r * 64 + ps * 4) * 4),
                           &gsrc[v]);
            }
        }
        cp_commit();
    };

    // Prime pipeline (distance 2): chunks 0,1 of first tile.
    prefetch(tile_cur, 0, 0);
    prefetch(tile_cur, 1, 1);

    const float4* __restrict__ w0v = reinterpret_cast<const float4*>(sW[0]);
    const float4* __restrict__ w1v = reinterpret_cast<const float4*>(sW[1]);
    const float4* __restrict__ w2v = reinterpret_cast<const float4*>(sW[2]);

    const int r = t >> 2;            // my row within chunk (0..31)
    const int a = t & 3;             // my lane within row-group (0..3)
    const int rswz = (r & 1) << 2;   // my row's slot swizzle

    int item = 0;

    while (tile_cur < ntiles) {
        #pragma unroll
        for (int q = 0; q < 4; ++q, ++item) {
            cp_wait<1>();
            __syncthreads();   // buffer (item%NBUF) staged; prior reads done

            if (q == 0) tile_next = s_next;   // stolen at prev tile's q==3

            const int row = tile_cur * TILE_ROWS + q * CHUNK + r;
            const bool live = (row < N);

            // Leader lane prefetches lab early.
            float l0 = 0.f, l1 = 0.f, l2 = 0.f;
            if (a == 0 && live) {
                const float* lr = lab + (size_t)row * 3;
                l0 = __ldg(&lr[0]); l1 = __ldg(&lr[1]); l2 = __ldg(&lr[2]);
            }

            const float4* __restrict__ dv =
                reinterpret_cast<const float4*>(&sbuf[item % NBUF][r * 64]);

            float acc0 = 0.f, acc1 = 0.f, acc2 = 0.f;
            #pragma unroll
            for (int k = 0; k < 4; ++k) {
                int s  = 4 * k + a;            // logical slot
                float4 d  = dv[s ^ rswz];      // undo swizzle
                float4 w0 = w0v[s];
                float4 w1 = w1v[s];
                float4 w2 = w2v[s];
                acc0 += d.x * w0.x + d.y * w0.y + d.z * w0.z + d.w * w0.w;
                acc1 += d.x * w1.x + d.y * w1.y + d.z * w1.z + d.w * w1.w;
                acc2 += d.x * w2.x + d.y * w2.y + d.z * w2.z + d.w * w2.w;
            }

            // Reduce across the 4 lanes of this row.
            #pragma unroll
            for (int off = 1; off <= 2; off <<= 1) {
                acc0 += __shfl_xor_sync(0xFFFFFFFFu, acc0, off);
                acc1 += __shfl_xor_sync(0xFFFFFFFFu, acc1, off);
                acc2 += __shfl_xor_sync(0xFFFFFFFFu, acc2, off);
            }

            if (a == 0 && live) {
                float p0 = acc0 + sb[0];
                float p1 = acc1 + sb[1];
                float p2 = acc2 + sb[2];

                float n = sqrtf(p0 * p0 + p1 * p1 + p2 * p2);
                float inv = 1.0f / fmaxf(n, EPS);
                float pn0 = p0 * inv, pn1 = p1 * inv, pn2 = p2 * inv;

                float dot = pn0 * l0 + pn1 * l1 + pn2 * l2;
                float na = fmaxf(sqrtf(pn0*pn0 + pn1*pn1 + pn2*pn2), EPS);
                float nb = fmaxf(sqrtf(l0*l0 + l1*l1 + l2*l2), EPS);
                float cosv = dot / (na * nb);

                float loss = acosf(cosv) * RAD2DEG;
                if (isnan(loss)) loss = 0.0f;
                __stcs(&out[row], loss);
            }

            // Steal the tile after tile_next (consumed at next q==0).
            if (q == 3 && t == 0 && tile_next < ntiles)
                s_next = nblk + (int)atomicAdd(&g_tile_ctr, 1u);

            // Prefetch item+2: chunk (q+2)&3 of tile_cur (q<2) or tile_next.
            int pq    = (q + 2) & 3;
            int ptile = (q < 2) ? tile_cur : tile_next;
            prefetch(ptile, pq, (item + 2) % NBUF);
        }

        tile_cur = tile_next;
    }

    // Last CTA out resets the counters for the next graph replay.
    __syncthreads();
    if (t == 0) {
        __threadfence();
        unsigned int d = atomicAdd(&g_done_ctr, 1u);
        if (d == (unsigned int)nblk - 1u) {
            g_tile_ctr = 0u;
            g_done_ctr = 0u;
            __threadfence();
        }
    }
}

extern "C" void kernel_launch(void* const* d_in, const int* in_sizes, int n_in,
                              void* d_out, int out_size)
{
    const float* data = (const float*)d_in[0];
    const float* lab  = (const float*)d_in[1];
    const float* W    = (const float*)d_in[2];
    const float* b    = (const float*)d_in[3];
    float* out = (float*)d_out;

    int N = in_sizes[0] / 64;
    int ntiles = (N + TILE_ROWS - 1) / TILE_ROWS;
    int blocks = 148 * 8;
    if (blocks > ntiles) blocks = ntiles;

    cosine_loss_kernel<<<blocks, THREADS>>>(data, lab, W, b, out, N, ntiles);
}

// round 14
// speedup vs baseline: 1.0350x; 1.0350x over previous
#include <cuda_runtime.h>
#include <cstdint>
#include <math.h>

#define EPS 1e-8f
#define RAD2DEG 57.295779513082320876798154814105f

#define THREADS    128
#define TILE_ROWS  128
#define CHUNK      32         // rows per item; 32 rows x 64 cols = 8KB contiguous
#define NBUF       3          // ring depth (>= prefetch distance 2 + 1)
#define BUF_F      (CHUNK * 64)

// Inputs: data [N,64] f32, lab [N,3] f32, W [64,3] f32, b [3] f32 ; out [N] f32
//
// Persistent CTAs + work stealing (self-resetting ticket counter).
// Each item = 32 contiguous rows (8KB) loaded by ONE cp.async.bulk issued by
// an elected thread, completing on an mbarrier (expect_tx). This removes all
// per-thread LDGSTS staging work from the issue/LSU path (R13 showed issue
// 63% / L1 71% with per-thread cp.async staging of the same chunks).
// Compute: 4 lanes per row; read-side bank fix: instr k reads slot
// 4*(k^(r&1))+a so even/odd rows hit complementary 16-bank halves.
// Sync: mbarrier parity wait (slot item%3, parity (item/3)&1) + one
// __syncthreads per item to guard slot reuse.

__device__ unsigned int g_tile_ctr = 0;
__device__ unsigned int g_done_ctr = 0;

__device__ __forceinline__ void mbar_init(unsigned int mbar, unsigned int cnt) {
    asm volatile("mbarrier.init.shared.b64 [%0], %1;"
                 :: "r"(mbar), "r"(cnt) : "memory");
}
__device__ __forceinline__ void mbar_expect_tx(unsigned int mbar, unsigned int bytes) {
    asm volatile("mbarrier.arrive.expect_tx.shared.b64 _, [%0], %1;"
                 :: "r"(mbar), "r"(bytes) : "memory");
}
__device__ __forceinline__ void bulk_g2s(unsigned int dst, const void* src,
                                         unsigned int bytes, unsigned int mbar) {
    asm volatile(
        "cp.async.bulk.shared::cta.global.mbarrier::complete_tx::bytes "
        "[%0], [%1], %2, [%3];"
        :: "r"(dst), "l"(src), "r"(bytes), "r"(mbar) : "memory");
}
__device__ __forceinline__ void mbar_wait(unsigned int mbar, unsigned int parity) {
    unsigned int done;
    asm volatile(
        "{\n\t.reg .pred p;\n\t"
        "mbarrier.try_wait.parity.shared.b64 p, [%1], %2;\n\t"
        "selp.b32 %0, 1, 0, p;\n\t}"
        : "=r"(done) : "r"(mbar), "r"(parity) : "memory");
    if (!done) {
        asm volatile(
            "{\n\t.reg .pred P1;\n\t"
            "WAIT_LOOP_%=:\n\t"
            "mbarrier.try_wait.parity.shared.b64 P1, [%0], %1;\n\t"
            "@P1 bra.uni WAIT_DONE_%=;\n\t"
            "bra.uni WAIT_LOOP_%=;\n\t"
            "WAIT_DONE_%=:\n\t}"
            :: "r"(mbar), "r"(parity) : "memory");
    }
}

__global__ __launch_bounds__(THREADS, 8) void cosine_loss_kernel(
    const float* __restrict__ data,
    const float* __restrict__ lab,
    const float* __restrict__ W,
    const float* __restrict__ b,
    float* __restrict__ out,
    int N, int ntiles)
{
    __shared__ __align__(128) float sbuf[NBUF][BUF_F];    // 3 x 8KB
    __shared__ __align__(16) float sW[3][64];
    __shared__ float sb[3];
    __shared__ __align__(8) unsigned long long s_mbar[NBUF];
    __shared__ int s_next;

    const int t = threadIdx.x;
    const int nblk = (int)gridDim.x;

    if (t < 192) { int k = t / 3, c = t % 3; sW[c][k] = W[t]; }
    {
        int i = t + 128;
        if (i < 192) { int k = i / 3, c = i % 3; sW[c][k] = W[i]; }
    }
    if (t < 3) sb[t] = b[t];

    const unsigned int mb0 =
        (unsigned int)__cvta_generic_to_shared(&s_mbar[0]);

    int tile_cur = blockIdx.x;
    if (t == 0) {
        #pragma unroll
        for (int s = 0; s < NBUF; ++s) mbar_init(mb0 + 8u * s, 1u);
        s_next = nblk + (int)atomicAdd(&g_tile_ctr, 1u);
    }
    __syncthreads();      // W/b staged, mbars init, s_next visible
    int tile_next = s_next;

    // Issue one bulk load: chunk q of `tile` -> sbuf[slot]. t==0 only.
    auto issue = [&](int tile, int q, int slot) {
        if (tile >= ntiles) return;
        int row0 = tile * TILE_ROWS + q * CHUNK;
        if (row0 >= N) return;
        int rows = min(CHUNK, N - row0);
        unsigned int bytes = (unsigned int)rows * 256u;
        unsigned int mbar = mb0 + 8u * slot;
        unsigned int dst =
            (unsigned int)__cvta_generic_to_shared(&sbuf[slot][0]);
        mbar_expect_tx(mbar, bytes);
        bulk_g2s(dst, data + (size_t)row0 * 64, bytes, mbar);
    };

    // Prime pipeline (distance 2).
    if (t == 0) {
        issue(tile_cur, 0, 0);
        issue(tile_cur, 1, 1);
    }

    const float4* __restrict__ w0v = reinterpret_cast<const float4*>(sW[0]);
    const float4* __restrict__ w1v = reinterpret_cast<const float4*>(sW[1]);
    const float4* __restrict__ w2v = reinterpret_cast<const float4*>(sW[2]);

    const int r = t >> 2;            // my row within chunk (0..31)
    const int a = t & 3;             // my lane within row-group (0..3)
    const int kx = r & 1;            // read-side k interleave for banks

    int slot = 0, par = 0, m3 = 0;   // slot = item%3, par = (item/3)&1

    while (tile_cur < ntiles) {
        #pragma unroll
        for (int q = 0; q < 4; ++q) {
            const unsigned int mbar = mb0 + 8u * slot;
            mbar_wait(mbar, (unsigned int)par);

            if (q == 0) tile_next = s_next;

            const int row = tile_cur * TILE_ROWS + q * CHUNK + r;
            const bool live = (row < N);

            float l0 = 0.f, l1 = 0.f, l2 = 0.f;
            if (a == 0 && live) {
                const float* lr = lab + (size_t)row * 3;
                l0 = __ldg(&lr[0]); l1 = __ldg(&lr[1]); l2 = __ldg(&lr[2]);
            }

            const float4* __restrict__ dv =
                reinterpret_cast<const float4*>(&sbuf[slot][r * 64]);

            float acc0 = 0.f, acc1 = 0.f, acc2 = 0.f;
            #pragma unroll
            for (int k = 0; k < 4; ++k) {
                int s  = 4 * (k ^ kx) + a;     // linear layout, bank-staggered
                float4 d  = dv[s];
                float4 w0 = w0v[s];
                float4 w1 = w1v[s];
                float4 w2 = w2v[s];
                acc0 += d.x * w0.x + d.y * w0.y + d.z * w0.z + d.w * w0.w;
                acc1 += d.x * w1.x + d.y * w1.y + d.z * w1.z + d.w * w1.w;
                acc2 += d.x * w2.x + d.y * w2.y + d.z * w2.z + d.w * w2.w;
            }

            #pragma unroll
            for (int off = 1; off <= 2; off <<= 1) {
                acc0 += __shfl_xor_sync(0xFFFFFFFFu, acc0, off);
                acc1 += __shfl_xor_sync(0xFFFFFFFFu, acc1, off);
                acc2 += __shfl_xor_sync(0xFFFFFFFFu, acc2, off);
            }

            if (a == 0 && live) {
                float p0 = acc0 + sb[0];
                float p1 = acc1 + sb[1];
                float p2 = acc2 + sb[2];

                float n = sqrtf(p0 * p0 + p1 * p1 + p2 * p2);
                float inv = 1.0f / fmaxf(n, EPS);
                float pn0 = p0 * inv, pn1 = p1 * inv, pn2 = p2 * inv;

                float dot = pn0 * l0 + pn1 * l1 + pn2 * l2;
                float na = fmaxf(sqrtf(pn0*pn0 + pn1*pn1 + pn2*pn2), EPS);
                float nb = fmaxf(sqrtf(l0*l0 + l1*l1 + l2*l2), EPS);
                float cosv = dot / (na * nb);

                float loss = acosf(cosv) * RAD2DEG;
                if (isnan(loss)) loss = 0.0f;
                out[row] = loss;
            }

            if (q == 3 && t == 0 && tile_next < ntiles)
                s_next = nblk + (int)atomicAdd(&g_tile_ctr, 1u);

            __syncthreads();   // all reads of slot (item+2)%3 (item-1) retired

            if (t == 0) {
                int pq    = (q + 2) & 3;
                int ptile = (q < 2) ? tile_cur : tile_next;
                int pslot = slot + 2; if (pslot >= NBUF) pslot -= NBUF;
                issue(ptile, pq, pslot);
            }

            // advance slot/parity: slot=item%3, par=(item/3)&1
            if (++slot == NBUF) slot = 0;
            if (++m3 == NBUF) { m3 = 0; par ^= 1; }
        }

        tile_cur = tile_next;
    }

    // Last CTA resets counters for the next graph replay.
    __syncthreads();
    if (t == 0) {
        __threadfence();
        unsigned int d = atomicAdd(&g_done_ctr, 1u);
        if (d == (unsigned int)nblk - 1u) {
            g_tile_ctr = 0u;
            g_done_ctr = 0u;
            __threadfence();
        }
    }
}

extern "C" void kernel_launch(void* const* d_in, const int* in_sizes, int n_in,
                              void* d_out, int out_size)
{
    const float* data = (const float*)d_in[0];
    const float* lab  = (const float*)d_in[1];
    const float* W    = (const float*)d_in[2];
    const float* b    = (const float*)d_in[3];
    float* out = (float*)d_out;

    int N = in_sizes[0] / 64;
    int ntiles = (N + TILE_ROWS - 1) / TILE_ROWS;
    int blocks = 148 * 8;
    if (blocks > ntiles) blocks = ntiles;

    cosine_loss_kernel<<<blocks, THREADS>>>(data, lab, W, b, out, N, ntiles);
}

// round 15
// speedup vs baseline: 1.1087x; 1.0712x over previous
#include <cuda_runtime.h>
#include <cstdint>
#include <math.h>

#define EPS 1e-8f
#define RAD2DEG 57.295779513082320876798154814105f

#define THREADS    128
#define TILE_ROWS  128
#define QCOLS      4          // float4 per row per quarter-tile (16 floats)
#define SSTRIDE    16         // floats per row (no pad; XOR swizzle)
#define NBUF       3          // ring depth (>= prefetch distance 2 + 1)

// Inputs: data [N,64] f32, lab [N,3] f32, W [64,3] f32, b [3] f32 ; out [N] f32
//
// BEST-MEASURED STRUCTURE (R10/R11): column-quarter cp.async ring
// (distance 2, one block barrier per item, 8 CTAs/SM), thread-per-row
// compute (no shuffles), dynamic work stealing, self-resetting counters.
// This round: unguarded fast path for full tiles (N % 128 == 0 in this
// problem), earlier ticket steal (q==1), __ldcs lab, minimal tail.

__device__ unsigned int g_tile_ctr = 0;   // tickets (tile = gridDim.x + k)
__device__ unsigned int g_done_ctr = 0;   // CTAs finished

__device__ __forceinline__ void cp_async16(unsigned int dst, const void* src) {
    asm volatile("cp.async.cg.shared.global [%0], [%1], 16;\n"
                 :: "r"(dst), "l"(src));
}
__device__ __forceinline__ void cp_commit() {
    asm volatile("cp.async.commit_group;\n");
}
template <int n>
__device__ __forceinline__ void cp_wait() {
    asm volatile("cp.async.wait_group %0;\n" :: "n"(n));
}

__global__ __launch_bounds__(THREADS, 8) void cosine_loss_kernel(
    const float* __restrict__ data,
    const float* __restrict__ lab,
    const float* __restrict__ W,
    const float* __restrict__ b,
    float* __restrict__ out,
    int N, int ntiles)
{
    __shared__ __align__(16) float sbuf[NBUF][TILE_ROWS * SSTRIDE]; // 3 x 8KB
    __shared__ __align__(16) float sW[3][64];
    __shared__ float sb[3];
    __shared__ int s_next;

    const int t = threadIdx.x;
    const int nblk = (int)gridDim.x;

    if (t < 192) { int k = t / 3, c = t % 3; sW[c][k] = W[t]; }
    {
        int i = t + 128;
        if (i < 192) { int k = i / 3, c = i % 3; sW[c][k] = W[i]; }
    }
    if (t < 3) sb[t] = b[t];

    int tile_cur = blockIdx.x;
    if (t == 0) s_next = nblk + (int)atomicAdd(&g_tile_ctr, 1u);
    __syncthreads();                       // W/b staged + s_next visible
    int tile_next = s_next;

    // Stage quarter q of `tile` into sbuf[slot].
    auto prefetch = [&](int tile, int q, int slot) {
        if (tile >= ntiles) { cp_commit(); return; }
        int row0 = tile * TILE_ROWS;
        const float4* gsrc = reinterpret_cast<const float4*>(data);
        unsigned int sdst =
            (unsigned int)__cvta_generic_to_shared(&sbuf[slot][0]);
        if (row0 + TILE_ROWS <= N) {
            // FULL TILE: no per-load guard.
            #pragma unroll
            for (int j = 0; j < QCOLS; ++j) {
                int v = j * THREADS + t;
                int r = v >> 2;
                int c = v & 3;
                int cs = c ^ ((r >> 1) & 3);
                cp_async16(sdst + (unsigned int)((r * SSTRIDE + cs * 4) * 4),
                           &gsrc[(size_t)(row0 + r) * 16 + q * QCOLS + c]);
            }
        } else {
            #pragma unroll
            for (int j = 0; j < QCOLS; ++j) {
                int v = j * THREADS + t;
                int r = v >> 2;
                int c = v & 3;
                int cs = c ^ ((r >> 1) & 3);
                if (row0 + r < N)
                    cp_async16(sdst + (unsigned int)((r * SSTRIDE + cs * 4) * 4),
                               &gsrc[(size_t)(row0 + r) * 16 + q * QCOLS + c]);
            }
        }
        cp_commit();
    };

    // Prime pipeline (distance 2): quarters 0,1 of the first tile.
    prefetch(tile_cur, 0, 0);
    prefetch(tile_cur, 1, 1);

    const float4* __restrict__ w0v = reinterpret_cast<const float4*>(sW[0]);
    const float4* __restrict__ w1v = reinterpret_cast<const float4*>(sW[1]);
    const float4* __restrict__ w2v = reinterpret_cast<const float4*>(sW[2]);

    const int myswz = (t >> 1) & 3;

    float acc0 = 0.f, acc1 = 0.f, acc2 = 0.f;
    float l0 = 0.f, l1 = 0.f, l2 = 0.f;
    int item = 0;

    while (tile_cur < ntiles) {
        const int row  = tile_cur * TILE_ROWS + t;
        const bool live = (row < N);

        #pragma unroll
        for (int q = 0; q < 4; ++q, ++item) {
            cp_wait<1>();
            __syncthreads();   // buffer (item%NBUF) staged; prior reads done

            if (q == 0) {
                tile_next = s_next;            // stolen at prev tile's q==1
                acc0 = acc1 = acc2 = 0.f;
                if (live) {
                    const float* lr = lab + (size_t)row * 3;
                    l0 = __ldcs(&lr[0]); l1 = __ldcs(&lr[1]); l2 = __ldcs(&lr[2]);
                }
            }

            // Steal the tile after tile_next early (consumed at next q==0):
            // ~3 items of slack over the global-atomic latency.
            if (q == 1 && t == 0 && tile_next < ntiles)
                s_next = nblk + (int)atomicAdd(&g_tile_ctr, 1u);

            const float4* __restrict__ dv =
                reinterpret_cast<const float4*>(&sbuf[item % NBUF][t * SSTRIDE]);

            #pragma unroll
            for (int k = 0; k < QCOLS; ++k) {
                float4 d  = dv[k ^ myswz];
                int kk = q * QCOLS + k;
                float4 w0 = w0v[kk];
                float4 w1 = w1v[kk];
                float4 w2 = w2v[kk];
                acc0 += d.x * w0.x + d.y * w0.y + d.z * w0.z + d.w * w0.w;
                acc1 += d.x * w1.x + d.y * w1.y + d.z * w1.z + d.w * w1.w;
                acc2 += d.x * w2.x + d.y * w2.y + d.z * w2.z + d.w * w2.w;
            }

            if (q == 3 && live) {
                float p0 = acc0 + sb[0];
                float p1 = acc1 + sb[1];
                float p2 = acc2 + sb[2];

                float n = sqrtf(p0 * p0 + p1 * p1 + p2 * p2);
                float inv = 1.0f / fmaxf(n, EPS);
                float pn0 = p0 * inv, pn1 = p1 * inv, pn2 = p2 * inv;

                float dot = pn0 * l0 + pn1 * l1 + pn2 * l2;
                float na = fmaxf(sqrtf(pn0*pn0 + pn1*pn1 + pn2*pn2), EPS);
                float nb = fmaxf(sqrtf(l0*l0 + l1*l1 + l2*l2), EPS);
                float cosv = dot / (na * nb);

                float loss = acosf(cosv) * RAD2DEG;
                if (isnan(loss)) loss = 0.0f;
                __stcs(&out[row], loss);
            }

            // Prefetch item+2: quarter (q+2)&3 of tile_cur (q<2) or tile_next.
            int pq    = (q + 2) & 3;
            int ptile = (q < 2) ? tile_cur : tile_next;
            prefetch(ptile, pq, (item + 2) % NBUF);
        }

        tile_cur = tile_next;
    }

    // Last CTA resets counters for the next graph replay. A CTA's final
    // ticket atomicAdd strictly precedes its done-increment, so after the
    // last done-increment no ticket fetch can follow within this launch.
    if (t == 0) {
        __threadfence();
        unsigned int d = atomicAdd(&g_done_ctr, 1u);
        if (d == (unsigned int)nblk - 1u) {
            g_tile_ctr = 0u;
            g_done_ctr = 0u;
        }
    }
}

extern "C" void kernel_launch(void* const* d_in, const int* in_sizes, int n_in,
                              void* d_out, int out_size)
{
    const float* data = (const float*)d_in[0];
    const float* lab  = (const float*)d_in[1];
    const float* W    = (const float*)d_in[2];
    const float* b    = (const float*)d_in[3];
    float* out = (float*)d_out;

    int N = in_sizes[0] / 64;
    int ntiles = (N + TILE_ROWS - 1) / TILE_ROWS;
    int blocks = 148 * 8;
    if (blocks > ntiles) blocks = ntiles;

    cosine_loss_kernel<<<blocks, THREADS>>>(data, lab, W, b, out, N, ntiles);
}